// round 5
// baseline (speedup 1.0000x reference)
#include <cuda_runtime.h>
#include <cstdint>
#include <cstddef>

// Problem constants (fixed by reference setup_inputs)
#define BATCH  4
#define LQN    4096
#define LKN    4096
#define EMB    1024
#define NH     16
#define HD     64
#define BHN    (BATCH*NH)      // 64
#define NCHUNK 8
#define CHUNKK (LKN/NCHUNK)    // 512
#define QT     256             // q rows per phase2 CTA
#define SQS    260             // padded q-stride (multiple of 4)

typedef unsigned long long u64;
typedef unsigned int u32;

// 16-byte packed pair of f32x2 lanes, loaded with a single LDS.128.
// Ordinary C++ load -> correct ordering vs __syncthreads / smem stores.
struct alignas(16) U64x2 { u64 x, y; };

// Scratch (static __device__ — no allocation)
__device__ float g_kvp[(size_t)NCHUNK*BHN*HD*HD];  // partial kv
__device__ float g_ksp[(size_t)NCHUNK*BHN*HD];     // partial ksum
__device__ float g_kv [(size_t)BHN*HD*HD];         // reduced kv
__device__ float g_ks [(size_t)BHN*HD];            // reduced ksum

// ---------------- helpers ----------------
__device__ __forceinline__ float phi_sig(float x){
    // sigmoid(0.6053*x - 4.102) = 1/(1 + exp2(-0.8732633*x + 5.9179351))
    float t, r;
    float a = fmaf(x, -0.8732633f, 5.9179351f);
    asm("ex2.approx.ftz.f32 %0, %1;" : "=f"(t) : "f"(a));
    asm("rcp.approx.ftz.f32 %0, %1;" : "=f"(r) : "f"(1.0f + t));
    return r;
}
__device__ __forceinline__ u64 pk2(float a, float b){
    u64 r; asm("mov.b64 %0, {%1,%2};" : "=l"(r) : "f"(a), "f"(b)); return r;
}
__device__ __forceinline__ void upk2(u64 v, float& a, float& b){
    asm("mov.b64 {%0,%1}, %2;" : "=f"(a), "=f"(b) : "l"(v));
}
__device__ __forceinline__ u64 fma2(u64 a, u64 b, u64 c){
    u64 d; asm("fma.rn.f32x2 %0, %1, %2, %3;" : "=l"(d) : "l"(a), "l"(b), "l"(c)); return d;
}
__device__ __forceinline__ float rcpf(float x){
    float r; asm("rcp.approx.ftz.f32 %0, %1;" : "=f"(r) : "f"(x)); return r;
}

// ============================================================================
// Phase 1: kv partials = phi(K)^T @ V.  grid (BHN, NCHUNK), 256 threads.
// Compute: 4 k-groups x 64 threads; each thread 8d x 8e register tile.
// ksum folded into the loader (phi conversion) pass.
// ============================================================================
__global__ void __launch_bounds__(256, 2) la_phase1(const float* __restrict__ K,
                                                    const float* __restrict__ V){
    __shared__ alignas(16) float sK[32][64];
    __shared__ alignas(16) float sV[32][64];
    __shared__ alignas(16) float stage[64][64];
    __shared__ float ksst[16][64];

    const int tid = threadIdx.x;
    const int bh  = blockIdx.x;
    const int ck  = blockIdx.y;
    const int b   = bh >> 4;
    const int h   = bh & 15;
    const int k0  = ck * CHUNKK;

    const float* Kb = K + (size_t)b*LKN*EMB + (size_t)h*HD;
    const float* Vb = V + (size_t)b*LKN*EMB + (size_t)h*HD;

    // loader mapping: rows r0l and r0l+16, float4 col c4
    const int r0l = tid >> 4, c4 = tid & 15;
    const int r1l = r0l + 16;

    // compute mapping
    const int g  = tid >> 6;          // k-group 0..3
    const int lt = tid & 63;
    const int d0 = (lt >> 3) * 8;
    const int e0 = (lt & 7) * 8;

    u64 acc[8][4];
    #pragma unroll
    for(int i=0;i<8;i++){ acc[i][0]=acc[i][1]=acc[i][2]=acc[i][3]=0ull; }
    float ksl[4] = {0.f,0.f,0.f,0.f};

    float4 pk0, pk1, pv0, pv1;
    pk0 = *(const float4*)(Kb + (size_t)(k0 + r0l)*EMB + c4*4);
    pk1 = *(const float4*)(Kb + (size_t)(k0 + r1l)*EMB + c4*4);
    pv0 = *(const float4*)(Vb + (size_t)(k0 + r0l)*EMB + c4*4);
    pv1 = *(const float4*)(Vb + (size_t)(k0 + r1l)*EMB + c4*4);

    const int NT = CHUNKK / 32;   // 16
    for(int t=0; t<NT; t++){
        __syncthreads();
        {
            float f00=phi_sig(pk0.x), f01=phi_sig(pk0.y), f02=phi_sig(pk0.z), f03=phi_sig(pk0.w);
            float f10=phi_sig(pk1.x), f11=phi_sig(pk1.y), f12=phi_sig(pk1.z), f13=phi_sig(pk1.w);
            sK[r0l][c4*4+0]=f00; sK[r0l][c4*4+1]=f01; sK[r0l][c4*4+2]=f02; sK[r0l][c4*4+3]=f03;
            sK[r1l][c4*4+0]=f10; sK[r1l][c4*4+1]=f11; sK[r1l][c4*4+2]=f12; sK[r1l][c4*4+3]=f13;
            ksl[0]+=f00+f10; ksl[1]+=f01+f11; ksl[2]+=f02+f12; ksl[3]+=f03+f13;
            *(float4*)&sV[r0l][c4*4] = pv0;
            *(float4*)&sV[r1l][c4*4] = pv1;
        }
        __syncthreads();
        if(t+1 < NT){
            int kb = k0 + (t+1)*32;
            pk0 = *(const float4*)(Kb + (size_t)(kb + r0l)*EMB + c4*4);
            pk1 = *(const float4*)(Kb + (size_t)(kb + r1l)*EMB + c4*4);
            pv0 = *(const float4*)(Vb + (size_t)(kb + r0l)*EMB + c4*4);
            pv1 = *(const float4*)(Vb + (size_t)(kb + r1l)*EMB + c4*4);
        }
        #pragma unroll
        for(int kk=0; kk<8; kk++){
            const int k = g*8 + kk;
            float4 a0 = *(const float4*)&sK[k][d0];
            float4 a1 = *(const float4*)&sK[k][d0+4];
            const U64x2* vrow = (const U64x2*)&sV[k][e0];
            U64x2 vA = vrow[0];
            U64x2 vB = vrow[1];
            float a_[8] = {a0.x,a0.y,a0.z,a0.w,a1.x,a1.y,a1.z,a1.w};
            #pragma unroll
            for(int i=0;i<8;i++){
                u64 pa = pk2(a_[i], a_[i]);
                acc[i][0] = fma2(pa, vA.x, acc[i][0]);
                acc[i][1] = fma2(pa, vA.y, acc[i][1]);
                acc[i][2] = fma2(pa, vB.x, acc[i][2]);
                acc[i][3] = fma2(pa, vB.y, acc[i][3]);
            }
        }
    }

    // ksum partials into smem
    ksst[r0l][c4*4+0]=ksl[0]; ksst[r0l][c4*4+1]=ksl[1];
    ksst[r0l][c4*4+2]=ksl[2]; ksst[r0l][c4*4+3]=ksl[3];
    __syncthreads();

    // cross-k-group combine of kv into stage (serialized over 4 groups)
    for(int gg=0; gg<4; gg++){
        if(g == gg){
            #pragma unroll
            for(int i=0;i<8;i++){
                float4 x0, x1;
                upk2(acc[i][0], x0.x, x0.y); upk2(acc[i][1], x0.z, x0.w);
                upk2(acc[i][2], x1.x, x1.y); upk2(acc[i][3], x1.z, x1.w);
                if(gg > 0){
                    float4 s0 = *(float4*)&stage[d0+i][e0];
                    float4 s1 = *(float4*)&stage[d0+i][e0+4];
                    x0.x+=s0.x; x0.y+=s0.y; x0.z+=s0.z; x0.w+=s0.w;
                    x1.x+=s1.x; x1.y+=s1.y; x1.z+=s1.z; x1.w+=s1.w;
                }
                *(float4*)&stage[d0+i][e0]   = x0;
                *(float4*)&stage[d0+i][e0+4] = x1;
            }
        }
        __syncthreads();
    }

    // write partial kv + ksum
    float4* dst = (float4*)(g_kvp + (size_t)(ck*BHN + bh)*HD*HD);
    #pragma unroll
    for(int i=0;i<4;i++) dst[tid + i*256] = ((float4*)stage)[tid + i*256];
    if(tid < HD){
        float s = 0.0f;
        #pragma unroll
        for(int i=0;i<16;i++) s += ksst[i][tid];
        g_ksp[(size_t)(ck*BHN + bh)*HD + tid] = s;
    }
}

// ============================================================================
// Reduce partials
// ============================================================================
__global__ void __launch_bounds__(256) la_reduce(){
    const int bh = blockIdx.x;
    const int tid = threadIdx.x;
    for(int idx = tid; idx < HD*HD; idx += 256){
        float s = 0.0f;
        #pragma unroll
        for(int c=0;c<NCHUNK;c++)
            s += g_kvp[(size_t)(c*BHN + bh)*HD*HD + idx];
        g_kv[(size_t)bh*HD*HD + idx] = s;
    }
    if(tid < HD){
        float s = 0.0f;
        #pragma unroll
        for(int c=0;c<NCHUNK;c++)
            s += g_ksp[(size_t)(c*BHN + bh)*HD + tid];
        g_ks[(size_t)bh*HD + tid] = s;
    }
}

// ============================================================================
// Phase 2: out = (phi(Q)@kv) / den, den precomputed during A construction.
// grid (BHN, 16), 256 threads. Thread (qg 0..31, eg 0..7): 8q x 8e tile.
// ============================================================================
extern __shared__ float smp2[];
__global__ void __launch_bounds__(256, 2) la_phase2(const float* __restrict__ Q,
                                                    float* __restrict__ out){
    float* sQt = smp2;                  // [HD][SQS] transposed phi(Q)
    float* sKV = smp2 + HD*SQS;         // [HD][HD]
    float* dpp = sKV + HD*HD;           // [QT][16] den partials
    float* den = dpp + QT*16;           // [QT]

    const int tid = threadIdx.x;
    const int bh  = blockIdx.x;
    const int qt  = blockIdx.y;
    const int b   = bh >> 4;
    const int h   = bh & 15;
    const int q0  = qt * QT;

    // ---- construction: phi(Q) transposed + den partials ----
    {
        const int lr = tid >> 4, c4 = tid & 15;
        float4 ks4 = *(const float4*)(g_ks + (size_t)bh*HD + c4*4);
        const float* Qb = Q + ((size_t)b*LQN + q0)*EMB + (size_t)h*HD;
        #pragma unroll
        for(int p=0;p<16;p++){
            int row = p*16 + lr;
            float4 v = *(const float4*)(Qb + (size_t)row*EMB + c4*4);
            float p0=phi_sig(v.x), p1=phi_sig(v.y), p2=phi_sig(v.z), p3=phi_sig(v.w);
            sQt[(c4*4+0)*SQS + row] = p0;
            sQt[(c4*4+1)*SQS + row] = p1;
            sQt[(c4*4+2)*SQS + row] = p2;
            sQt[(c4*4+3)*SQS + row] = p3;
            dpp[row*16 + c4] = fmaf(p0,ks4.x, fmaf(p1,ks4.y, fmaf(p2,ks4.z, p3*ks4.w)));
        }
    }
    // ---- kv tile ----
    {
        const float4* kvsrc = (const float4*)(g_kv + (size_t)bh*HD*HD);
        #pragma unroll
        for(int i=0;i<4;i++)
            ((float4*)sKV)[tid + i*256] = kvsrc[tid + i*256];
    }
    __syncthreads();
    // ---- den reduce ----
    {
        float s = 0.0f;
        #pragma unroll
        for(int j=0;j<16;j++) s += dpp[tid*16 + j];
        den[tid] = s;
    }
    __syncthreads();

    // ---- main loop ----
    const int qg = tid >> 3;
    const int eg = tid & 7;

    u64 acc[8][4];
    #pragma unroll
    for(int q=0;q<8;q++){ acc[q][0]=acc[q][1]=acc[q][2]=acc[q][3]=0ull; }

    const float* aBase  = sQt + qg*8;
    const float* kvBase = sKV + eg*8;

    #pragma unroll 8
    for(int d=0; d<HD; d++){
        float4 a0 = *(const float4*)(aBase + (size_t)d*SQS);
        float4 a1 = *(const float4*)(aBase + (size_t)d*SQS + 4);
        const U64x2* krow = (const U64x2*)(kvBase + (size_t)d*HD);
        U64x2 kA = krow[0];
        U64x2 kB = krow[1];
        float a_[8] = {a0.x,a0.y,a0.z,a0.w,a1.x,a1.y,a1.z,a1.w};
        #pragma unroll
        for(int q=0;q<8;q++){
            u64 pa = pk2(a_[q], a_[q]);
            acc[q][0] = fma2(pa, kA.x, acc[q][0]);
            acc[q][1] = fma2(pa, kA.y, acc[q][1]);
            acc[q][2] = fma2(pa, kB.x, acc[q][2]);
            acc[q][3] = fma2(pa, kB.y, acc[q][3]);
        }
    }

    // ---- epilogue ----
    float* ob = out + ((size_t)b*LQN + q0 + qg*8)*EMB + (size_t)h*HD + eg*8;
    #pragma unroll
    for(int q=0;q<8;q++){
        float rd = rcpf(den[qg*8 + q]);
        float4 o0, o1;
        upk2(acc[q][0], o0.x, o0.y); upk2(acc[q][1], o0.z, o0.w);
        upk2(acc[q][2], o1.x, o1.y); upk2(acc[q][3], o1.z, o1.w);
        o0.x*=rd; o0.y*=rd; o0.z*=rd; o0.w*=rd;
        o1.x*=rd; o1.y*=rd; o1.z*=rd; o1.w*=rd;
        *(float4*)(ob + (size_t)q*EMB)     = o0;
        *(float4*)(ob + (size_t)q*EMB + 4) = o1;
    }
}

// ---------------- launch ----------------
extern "C" void kernel_launch(void* const* d_in, const int* in_sizes, int n_in,
                              void* d_out, int out_size){
    const float* Q = (const float*)d_in[0];
    const float* K = (const float*)d_in[1];
    const float* V = (const float*)d_in[2];
    float* out = (float*)d_out;

    const int smem2 = (HD*SQS + HD*HD + QT*16 + QT) * sizeof(float);  // ~100KB
    cudaFuncSetAttribute(la_phase2, cudaFuncAttributeMaxDynamicSharedMemorySize, smem2);

    la_phase1<<<dim3(BHN, NCHUNK), 256>>>(K, V);
    la_reduce<<<BHN, 256>>>();
    la_phase2<<<dim3(BHN, LQN/QT), 256, smem2>>>(Q, out);
}

// round 7
// speedup vs baseline: 1.1530x; 1.1530x over previous
#include <cuda_runtime.h>
#include <cuda_bf16.h>
#include <cstdint>
#include <cstddef>

#define BATCH  4
#define LQN    4096
#define LKN    4096
#define EMB    1024
#define NH     16
#define HD     64
#define BHN    64
#define NCH2   16       // phase1 chunks
#define KCH    256      // k rows per phase1 CTA
#define KT1    32       // k rows per phase1 tile
#define SP1    40       // phase1 plane stride (u16): 80B, 16B-mult, conflict-free ldmatrix
#define SP2    72       // phase2 plane stride (u16): 144B, 16B-mult

typedef unsigned long long u64;
typedef unsigned int u32;
typedef unsigned short u16;

// Scratch (static __device__ — no allocation)
__device__ float g_kvp[(size_t)NCH2*BHN*HD*HD];   // fp32 kv partials (16 MB)
__device__ float g_ksp[(size_t)NCH2*BHN*HD];      // ksum partials
__device__ float g_ks [(size_t)BHN*HD];           // reduced ksum
__device__ u16   g_kvbh[(size_t)BHN*HD*HD];       // kv^T hi bf16 [bh][e][d]
__device__ u16   g_kvbl[(size_t)BHN*HD*HD];       // kv^T lo bf16

// ---------------- helpers ----------------
__device__ __forceinline__ float phi_sig(float x){
    // sigmoid(0.6053*x - 4.102) = 1/(1 + exp2(-0.8732633*x + 5.9179351))
    float t, r;
    float a = fmaf(x, -0.8732633f, 5.9179351f);
    asm("ex2.approx.ftz.f32 %0, %1;" : "=f"(t) : "f"(a));
    asm("rcp.approx.ftz.f32 %0, %1;" : "=f"(r) : "f"(1.0f + t));
    return r;
}
__device__ __forceinline__ float rcpf(float x){
    float r; asm("rcp.approx.ftz.f32 %0, %1;" : "=f"(r) : "f"(x)); return r;
}
__device__ __forceinline__ u32 sm32(const void* p){
    u32 a; asm("{ .reg .u64 t; cvta.to.shared.u64 t, %1; cvt.u32.u64 %0, t; }" : "=r"(a) : "l"(p));
    return a;
}
__device__ __forceinline__ void ldm4(u32* r, u32 addr){
    asm volatile("ldmatrix.sync.aligned.m8n8.x4.shared.b16 {%0,%1,%2,%3}, [%4];"
        : "=r"(r[0]),"=r"(r[1]),"=r"(r[2]),"=r"(r[3]) : "r"(addr));
}
__device__ __forceinline__ void mma_bf16(float* c, const u32* a, const u32* b){
    asm volatile("mma.sync.aligned.m16n8k16.row.col.f32.bf16.bf16.f32 "
        "{%0,%1,%2,%3}, {%4,%5,%6,%7}, {%8,%9}, {%0,%1,%2,%3};"
        : "+f"(c[0]),"+f"(c[1]),"+f"(c[2]),"+f"(c[3])
        : "r"(a[0]),"r"(a[1]),"r"(a[2]),"r"(a[3]), "r"(b[0]),"r"(b[1]));
}
// split (x0,x1) into packed bf16 hi pair + lo pair (x = hi + lo to ~16 mantissa bits)
__device__ __forceinline__ void hilo2(float x0, float x1, u32& hp, u32& lp){
    __nv_bfloat16 h0 = __float2bfloat16_rn(x0);
    __nv_bfloat16 h1 = __float2bfloat16_rn(x1);
    float l0 = x0 - __bfloat162float(h0);
    float l1 = x1 - __bfloat162float(h1);
    __nv_bfloat16 q0 = __float2bfloat16_rn(l0);
    __nv_bfloat16 q1 = __float2bfloat16_rn(l1);
    hp = (u32)__bfloat16_as_ushort(h0) | ((u32)__bfloat16_as_ushort(h1) << 16);
    lp = (u32)__bfloat16_as_ushort(q0) | ((u32)__bfloat16_as_ushort(q1) << 16);
}

// ============================================================================
// Phase 1: kv = phi(K)^T @ V per (bh, chunk) via bf16 mma.sync (hi/lo 3-term).
// grid (BHN, NCH2), 128 threads (4 warps, warp w owns d-tile [w*16, w*16+16)).
// smem planes stored transposed: Fh/Fl [d][k], Vh/Vl [e][k], stride SP1.
// ============================================================================
__global__ void __launch_bounds__(128, 4) la_phase1(const float* __restrict__ K,
                                                    const float* __restrict__ V){
    __shared__ __align__(16) u16 pl[2][4][HD*SP1];   // [stage][Fh,Fl,Vh,Vl]
    __shared__ float ksst[16][64];

    const int tid  = threadIdx.x;
    const int lane = tid & 31;
    const int wid  = tid >> 5;
    const int bh   = blockIdx.x;
    const int ck   = blockIdx.y;
    const int b    = bh >> 4;
    const int h    = bh & 15;
    const int k0   = ck * KCH;

    const float* Kb = K + (size_t)b*LKN*EMB + (size_t)h*HD;
    const float* Vb = V + (size_t)b*LKN*EMB + (size_t)h*HD;

    const int kp = tid & 15;      // k-pair index within tile (k = 2*kp, 2*kp+1)
    const int c8 = tid >> 4;      // d/e octet (0..7)

    // ldmatrix lane offsets (u16 units; add s*16 for k-step)
    const int d0 = wid * 16;
    const u32 aoff = (u32)((d0 + (lane&7) + ((lane>>3)&1)*8)*SP1 + ((lane>>4)&1)*8);
    u32 boff[4];
    #pragma unroll
    for(int g2=0; g2<4; g2++)
        boff[g2] = (u32)(((lane&7) + ((lane>>4)&1)*8 + g2*16)*SP1 + ((lane>>3)&1)*8);

    u32 plb[2][4];
    #pragma unroll
    for(int s_=0;s_<2;s_++)
        #pragma unroll
        for(int p_=0;p_<4;p_++) plb[s_][p_] = sm32(&pl[s_][p_][0]);

    float acc[8][4];
    #pragma unroll
    for(int i=0;i<8;i++){ acc[i][0]=acc[i][1]=acc[i][2]=acc[i][3]=0.f; }
    float ks8[8] = {0.f,0.f,0.f,0.f,0.f,0.f,0.f,0.f};

    // staging registers for one tile (rows 2kp, 2kp+1; cols c8*8..+7)
    float fk0[8], fk1[8], fv0[8], fv1[8];

    // prefetch tile 0
    {
        const float* kr = Kb + (size_t)(k0 + kp*2)*EMB + c8*8;
        const float* vr = Vb + (size_t)(k0 + kp*2)*EMB + c8*8;
        *(float4*)&fk0[0] = *(const float4*)(kr);     *(float4*)&fk0[4] = *(const float4*)(kr+4);
        *(float4*)&fk1[0] = *(const float4*)(kr+EMB); *(float4*)&fk1[4] = *(const float4*)(kr+EMB+4);
        *(float4*)&fv0[0] = *(const float4*)(vr);     *(float4*)&fv0[4] = *(const float4*)(vr+4);
        *(float4*)&fv1[0] = *(const float4*)(vr+EMB); *(float4*)&fv1[4] = *(const float4*)(vr+EMB+4);
    }

    int st = 0;
    const int NT = KCH / KT1;   // 8
    for(int t=0; t<NT; t++){
        __syncthreads();   // stage st free (its mma finished in iteration t-2)
        // ---- convert + store tile t into stage st ----
        {
            u32 hp, lp;
            #pragma unroll
            for(int i=0;i<8;i++){
                float p0 = phi_sig(fk0[i]);
                float p1 = phi_sig(fk1[i]);
                ks8[i] += p0 + p1;
                hilo2(p0, p1, hp, lp);
                const int d = c8*8 + i;
                *(u32*)&pl[st][0][d*SP1 + kp*2] = hp;
                *(u32*)&pl[st][1][d*SP1 + kp*2] = lp;
            }
            #pragma unroll
            for(int i=0;i<8;i++){
                hilo2(fv0[i], fv1[i], hp, lp);
                const int e = c8*8 + i;
                *(u32*)&pl[st][2][e*SP1 + kp*2] = hp;
                *(u32*)&pl[st][3][e*SP1 + kp*2] = lp;
            }
        }
        __syncthreads();
        // ---- prefetch tile t+1 ----
        if(t+1 < NT){
            const float* kr = Kb + (size_t)(k0 + (t+1)*KT1 + kp*2)*EMB + c8*8;
            const float* vr = Vb + (size_t)(k0 + (t+1)*KT1 + kp*2)*EMB + c8*8;
            *(float4*)&fk0[0] = *(const float4*)(kr);     *(float4*)&fk0[4] = *(const float4*)(kr+4);
            *(float4*)&fk1[0] = *(const float4*)(kr+EMB); *(float4*)&fk1[4] = *(const float4*)(kr+EMB+4);
            *(float4*)&fv0[0] = *(const float4*)(vr);     *(float4*)&fv0[4] = *(const float4*)(vr+4);
            *(float4*)&fv1[0] = *(const float4*)(vr+EMB); *(float4*)&fv1[4] = *(const float4*)(vr+EMB+4);
        }
        // ---- mma over stage st: 2 k16 steps ----
        #pragma unroll
        for(int s=0; s<2; s++){
            u32 ah[4], al[4];
            ldm4(ah, plb[st][0] + (aoff + s*16)*2);
            ldm4(al, plb[st][1] + (aoff + s*16)*2);
            #pragma unroll
            for(int g2=0; g2<4; g2++){
                u32 bh4[4], bl4[4];
                ldm4(bh4, plb[st][2] + (boff[g2] + s*16)*2);
                ldm4(bl4, plb[st][3] + (boff[g2] + s*16)*2);
                mma_bf16(acc[g2*2],   ah, bh4);
                mma_bf16(acc[g2*2],   al, bh4);
                mma_bf16(acc[g2*2],   ah, bl4);
                mma_bf16(acc[g2*2+1], ah, bh4+2);
                mma_bf16(acc[g2*2+1], al, bh4+2);
                mma_bf16(acc[g2*2+1], ah, bl4+2);
            }
        }
        st ^= 1;
    }

    // ---- write fp32 kv partial ----
    {
        float* gp = g_kvp + ((size_t)(ck*BHN + bh))*HD*HD;
        const int g  = lane >> 2;
        const int tg = lane & 3;
        const int r0 = d0 + g, r1 = r0 + 8;
        #pragma unroll
        for(int n=0;n<8;n++){
            const int e = n*8 + tg*2;
            *(float2*)(gp + r0*HD + e) = make_float2(acc[n][0], acc[n][1]);
            *(float2*)(gp + r1*HD + e) = make_float2(acc[n][2], acc[n][3]);
        }
    }
    // ---- ksum partial ----
    #pragma unroll
    for(int i=0;i<8;i++) ksst[kp][c8*8+i] = ks8[i];
    __syncthreads();
    if(tid < HD){
        float s = 0.f;
        #pragma unroll
        for(int i=0;i<16;i++) s += ksst[i][tid];
        g_ksp[(size_t)(ck*BHN + bh)*HD + tid] = s;
    }
}

// ============================================================================
// Reduce: sum 16 partials -> g_ks fp32 + kv^T hi/lo bf16 planes for phase2.
// ============================================================================
__global__ void __launch_bounds__(256) la_reduce(){
    const int bh  = blockIdx.x;
    const int tid = threadIdx.x;
    for(int idx = tid; idx < HD*HD; idx += 256){
        float s = 0.f;
        #pragma unroll
        for(int c=0;c<NCH2;c++)
            s += g_kvp[((size_t)c*BHN + bh)*HD*HD + idx];
        const int d = idx >> 6, e = idx & 63;
        __nv_bfloat16 hi = __float2bfloat16_rn(s);
        __nv_bfloat16 lo = __float2bfloat16_rn(s - __bfloat162float(hi));
        g_kvbh[(size_t)bh*HD*HD + e*HD + d] = __bfloat16_as_ushort(hi);
        g_kvbl[(size_t)bh*HD*HD + e*HD + d] = __bfloat16_as_ushort(lo);
    }
    if(tid < HD){
        float s = 0.f;
        #pragma unroll
        for(int c=0;c<NCH2;c++)
            s += g_ksp[(size_t)(c*BHN + bh)*HD + tid];
        g_ks[(size_t)bh*HD + tid] = s;
    }
}

// ============================================================================
// Phase 2: out = (phi(Q)@kv)/den via bf16 mma.sync (hi/lo 3-term).
// grid (BHN, 32), 128 threads. Warp w: m-tiles q = w*32, w*32+16.
// ============================================================================
extern __shared__ u16 smp2[];
__global__ void __launch_bounds__(128, 4) la_phase2(const float* __restrict__ Q,
                                                    float* __restrict__ out){
    u16* qh  = smp2;                 // [128][SP2]
    u16* ql  = qh  + 128*SP2;
    u16* kvh = ql  + 128*SP2;        // [64][SP2]
    u16* kvl = kvh + 64*SP2;
    float* sden = (float*)(kvl + 64*SP2);   // [128]
    float* sks  = sden + 128;               // [64]

    const int tid  = threadIdx.x;
    const int lane = tid & 31;
    const int wid  = tid >> 5;
    const int bh   = blockIdx.x;
    const int qt   = blockIdx.y;
    const int b    = bh >> 4;
    const int h    = bh & 15;
    const int q0   = qt * 128;

    // ---- kv planes + ksum ----
    // Each thread owns a 32-u16 half row (4 x uint4) per plane.  (R6 fix:
    // previously only 16 of the 32 u16 were written -> NaN from uninit smem.)
    {
        const int e = tid >> 1, hf = tid & 1;
        const uint4* sh = (const uint4*)(g_kvbh + (size_t)bh*HD*HD + e*HD + hf*32);
        const uint4* sl = (const uint4*)(g_kvbl + (size_t)bh*HD*HD + e*HD + hf*32);
        #pragma unroll
        for(int i=0;i<4;i++){
            uint4 a_ = sh[i];
            uint4 c_ = sl[i];
            *(uint4*)&kvh[e*SP2 + hf*32 + i*8] = a_;
            *(uint4*)&kvl[e*SP2 + hf*32 + i*8] = c_;
        }
        if(tid < HD) sks[tid] = g_ks[(size_t)bh*HD + tid];
    }
    __syncthreads();

    // ---- phi(Q) planes + den (thread = q row) ----
    {
        const float* Qr = Q + ((size_t)(b*LQN + q0 + tid))*EMB + (size_t)h*HD;
        float den = 0.f;
        #pragma unroll
        for(int j=0;j<8;j++){
            float f[8];
            *(float4*)&f[0] = *(const float4*)(Qr + j*8);
            *(float4*)&f[4] = *(const float4*)(Qr + j*8 + 4);
            float p[8];
            #pragma unroll
            for(int i=0;i<8;i++){
                p[i] = phi_sig(f[i]);
                den = fmaf(p[i], sks[j*8+i], den);
            }
            #pragma unroll
            for(int pr=0;pr<4;pr++){
                u32 hp, lp;
                hilo2(p[pr*2], p[pr*2+1], hp, lp);
                const int d = j*8 + pr*2;
                *(u32*)&qh[tid*SP2 + d] = hp;
                *(u32*)&ql[tid*SP2 + d] = lp;
            }
        }
        sden[tid] = den;
    }
    __syncthreads();

    // ---- mma ----
    const u32 qhB = sm32(qh), qlB = sm32(ql), kvhB = sm32(kvh), kvlB = sm32(kvl);
    const u32 arow = (u32)(((lane&7) + ((lane>>3)&1)*8)*SP2 + ((lane>>4)&1)*8);
    u32 boff[4];
    #pragma unroll
    for(int g2=0; g2<4; g2++)
        boff[g2] = (u32)(((lane&7) + ((lane>>4)&1)*8 + g2*16)*SP2 + ((lane>>3)&1)*8);

    float acc[2][8][4];
    #pragma unroll
    for(int u_=0;u_<2;u_++)
        #pragma unroll
        for(int n=0;n<8;n++){ acc[u_][n][0]=acc[u_][n][1]=acc[u_][n][2]=acc[u_][n][3]=0.f; }

    #pragma unroll
    for(int s=0; s<4; s++){
        u32 Bh_[4][4], Bl_[4][4];
        #pragma unroll
        for(int g2=0; g2<4; g2++){
            ldm4(Bh_[g2], kvhB + (boff[g2] + s*16)*2);
            ldm4(Bl_[g2], kvlB + (boff[g2] + s*16)*2);
        }
        #pragma unroll
        for(int u_=0; u_<2; u_++){
            const u32 ab = (arow + (u32)((wid*32 + u_*16)*SP2) + s*16)*2;
            u32 ah[4], al[4];
            ldm4(ah, qhB + ab);
            ldm4(al, qlB + ab);
            #pragma unroll
            for(int g2=0; g2<4; g2++){
                mma_bf16(acc[u_][g2*2],   ah, Bh_[g2]);
                mma_bf16(acc[u_][g2*2],   al, Bh_[g2]);
                mma_bf16(acc[u_][g2*2],   ah, Bl_[g2]);
                mma_bf16(acc[u_][g2*2+1], ah, Bh_[g2]+2);
                mma_bf16(acc[u_][g2*2+1], al, Bh_[g2]+2);
                mma_bf16(acc[u_][g2*2+1], ah, Bl_[g2]+2);
            }
        }
    }

    // ---- epilogue: divide by den, store ----
    {
        const int g  = lane >> 2;
        const int tg = lane & 3;
        #pragma unroll
        for(int u_=0; u_<2; u_++){
            const int qa = wid*32 + u_*16 + g;
            const int qb = qa + 8;
            const float rda = rcpf(sden[qa]);
            const float rdb = rcpf(sden[qb]);
            float* ra = out + ((size_t)(b*LQN + q0 + qa))*EMB + (size_t)h*HD;
            float* rb = out + ((size_t)(b*LQN + q0 + qb))*EMB + (size_t)h*HD;
            #pragma unroll
            for(int n=0;n<8;n++){
                const int e = n*8 + tg*2;
                *(float2*)(ra + e) = make_float2(acc[u_][n][0]*rda, acc[u_][n][1]*rda);
                *(float2*)(rb + e) = make_float2(acc[u_][n][2]*rdb, acc[u_][n][3]*rdb);
            }
        }
    }
}

// ---------------- launch ----------------
extern "C" void kernel_launch(void* const* d_in, const int* in_sizes, int n_in,
                              void* d_out, int out_size){
    const float* Q = (const float*)d_in[0];
    const float* K = (const float*)d_in[1];
    const float* V = (const float*)d_in[2];
    float* out = (float*)d_out;

    const int smem2 = (2*128*SP2 + 2*64*SP2)*2 + (128 + 64)*4;   // ~56 KB
    cudaFuncSetAttribute(la_phase2, cudaFuncAttributeMaxDynamicSharedMemorySize, smem2);

    la_phase1<<<dim3(BHN, NCH2), 128>>>(K, V);
    la_reduce<<<BHN, 256>>>();
    la_phase2<<<dim3(BHN, LQN/128), 128, smem2>>>(Q, out);
}